// round 10
// baseline (speedup 1.0000x reference)
#include <cuda_runtime.h>
#include <cuda_bf16.h>
#include <math.h>

// QuantumLayer as a multilinear polynomial (exact identity):
//   out_o(x) = T[o] . (1,cos x0,sin x0) x ... x (1,cos x3,sin x3)
// T (4 x 3^4, batch-constant) = circuit sampled at {0,pi/2,pi}^4 + inverse 3x3
// Vandermonde per axis. PDL: build_T triggers at its start; qlayer overlaps
// its prolog and gates the T read on cudaGridDependencySynchronize.
// R10: build_T warp-parallelized — 8 lanes per sample (each lane owns the amp
// pair (s, s+8)); RX butterflies via width-8 shfl_xor; CNOTs are shuffles.
// Cuts the primary from ~3 warps x 1500 serial FFMAs to ~200 instr/warp.
// Hot path: 4 sincos + 320 FMA/element (~85-88% of the FFMA-3reg chip floor).

__device__ __align__(16) float g_T[432];  // [o][k0][k1][k2][k3 padded to 4]

#define SHFL8(v, m) __shfl_xor_sync(0xFFFFFFFFu, (v), (m), 8)

// ---------------------------------------------------------------------------
// Kernel 1: build T. One block, 672 threads = 21 warps x 4 samples x 8 lanes.
// ---------------------------------------------------------------------------
__global__ void build_T_kernel(const float* __restrict__ w) {
    // Let the PDL secondary launch immediately; everything it does before
    // cudaGridDependencySynchronize() is T-independent.
    cudaTriggerProgrammaticLaunchCompletion();

    __shared__ float bufA[324], bufB[324];
    __shared__ float wc[12], wsn[12];
    const int t = threadIdx.x;

    if (t < 12) {
        float s, c;
        __sincosf(0.5f * w[t], &s, &c);
        wc[t] = c; wsn[t] = s;
    }
    __syncthreads();

    const int lane = t & 31;
    const int s    = lane & 7;              // slot: owns amps s and s+8
    const int sm   = (t >> 5) * 4 + (lane >> 3);  // sample id (0..83; >=81 garbage)

    // Sample digits (0..2 each) and half-angle cos/sin of {0, pi/2, pi}.
    const int a0 = sm / 27, a1 = (sm / 9) % 3, a2 = (sm / 3) % 3, a3 = sm % 3;
    const float R = 0.70710678118654752f;
    const float hc0 = (a0 == 0) ? 1.f : (a0 == 1) ? R : 0.f;
    const float hs0 = (a0 == 0) ? 0.f : (a0 == 1) ? R : 1.f;
    const float hc1 = (a1 == 0) ? 1.f : (a1 == 1) ? R : 0.f;
    const float hs1 = (a1 == 0) ? 0.f : (a1 == 1) ? R : 1.f;
    const float hc2 = (a2 == 0) ? 1.f : (a2 == 1) ? R : 0.f;
    const float hs2 = (a2 == 0) ? 0.f : (a2 == 1) ? R : 1.f;
    const float hc3 = (a3 == 0) ? 1.f : (a3 == 1) ? R : 0.f;
    const float hs3 = (a3 == 0) ? 0.f : (a3 == 1) ? R : 1.f;

    // Post-input-RX product state: amp_j = (-i)^popc(j) * prod_q f_q(bit(3-q))
    const float f1 = ((s >> 2) & 1) ? hs1 : hc1;   // qubit1 <-> bit2
    const float f2 = ((s >> 1) & 1) ? hs2 : hc2;   // qubit2 <-> bit1
    const float f3 = (s & 1)        ? hs3 : hc3;   // qubit3 <-> bit0
    const float rest = f1 * f2 * f3;
    const float m0 = hc0 * rest;   // amp j=s   (bit3=0)
    const float m1 = hs0 * rest;   // amp j=s+8 (bit3=1)

    const int pc0 = __popc(s) & 3;
    const int pc1 = (pc0 + 1) & 3;
    // (-i)^pc: 0->(1,0) 1->(0,-1) 2->(-1,0) 3->(0,1)
    float ar0 = (pc0 == 0) ?  m0 : (pc0 == 2) ? -m0 : 0.f;
    float ai0 = (pc0 == 1) ? -m0 : (pc0 == 3) ?  m0 : 0.f;
    float ar1 = (pc1 == 0) ?  m1 : (pc1 == 2) ? -m1 : 0.f;
    float ai1 = (pc1 == 1) ? -m1 : (pc1 == 3) ?  m1 : 0.f;

    // 3 layers: RX(w[l][q]) x4 then CNOT ring.
    // RX on bit b: new_j = c*a_j + (-i s)*a_{j^b}  (both butterfly members).
#pragma unroll
    for (int l = 0; l < 3; l++) {
        {   // q=0: bit8 -> partner is own other amp.
            const float cq = wc[l * 4 + 0], sq = wsn[l * 4 + 0];
            float nr0 = fmaf(cq, ar0,  sq * ai1);
            float ni0 = fmaf(cq, ai0, -sq * ar1);
            float nr1 = fmaf(cq, ar1,  sq * ai0);
            float ni1 = fmaf(cq, ai1, -sq * ar0);
            ar0 = nr0; ai0 = ni0; ar1 = nr1; ai1 = ni1;
        }
#pragma unroll
        for (int q = 1; q < 4; q++) {  // bits 4,2,1 -> partner slot s^b
            const int b = 8 >> q;
            const float cq = wc[l * 4 + q], sq = wsn[l * 4 + q];
            float pr0 = SHFL8(ar0, b), pi0 = SHFL8(ai0, b);
            float pr1 = SHFL8(ar1, b), pi1 = SHFL8(ai1, b);
            float nr0 = fmaf(cq, ar0,  sq * pi0);
            float ni0 = fmaf(cq, ai0, -sq * pr0);
            float nr1 = fmaf(cq, ar1,  sq * pi1);
            float ni1 = fmaf(cq, ai1, -sq * pr1);
            ar0 = nr0; ai0 = ni0; ar1 = nr1; ai1 = ni1;
        }
        // CNOT(0,1): ctrl bit3, tbit 4. amp0 unchanged; amp1 <- slot s^4's amp1.
        {
            float tr = SHFL8(ar1, 4), ti = SHFL8(ai1, 4);
            ar1 = tr; ai1 = ti;
        }
        // CNOT(1,2): ctrl bit2 (of s), tbit 2.
        {
            float pr0 = SHFL8(ar0, 2), pi0 = SHFL8(ai0, 2);
            float pr1 = SHFL8(ar1, 2), pi1 = SHFL8(ai1, 2);
            const bool ct = (s >> 2) & 1;
            ar0 = ct ? pr0 : ar0;  ai0 = ct ? pi0 : ai0;
            ar1 = ct ? pr1 : ar1;  ai1 = ct ? pi1 : ai1;
        }
        // CNOT(2,3): ctrl bit1 (of s), tbit 1.
        {
            float pr0 = SHFL8(ar0, 1), pi0 = SHFL8(ai0, 1);
            float pr1 = SHFL8(ar1, 1), pi1 = SHFL8(ai1, 1);
            const bool ct = (s >> 1) & 1;
            ar0 = ct ? pr0 : ar0;  ai0 = ct ? pi0 : ai0;
            ar1 = ct ? pr1 : ar1;  ai1 = ct ? pi1 : ai1;
        }
        // CNOT(3,0): ctrl bit0 (of s), tbit 8 -> in-thread amp swap when ctrl.
        {
            const bool ct = s & 1;
            float tr = ar0, ti = ai0;
            ar0 = ct ? ar1 : ar0;  ai0 = ct ? ai1 : ai0;
            ar1 = ct ? tr  : ar1;  ai1 = ct ? ti  : ai1;
        }
    }

    // Probabilities and the 4 signed (Walsh) sums, reduced over the 8 slots.
    const float p0 = ar0 * ar0 + ai0 * ai0;
    const float p1 = ar1 * ar1 + ai1 * ai1;
    const float tsum = p0 + p1, tdiff = p0 - p1;
    float v0 = tdiff;                                  // q=0 <-> bit3
    float v1 = ((s >> 2) & 1) ? -tsum : tsum;          // q=1 <-> bit2
    float v2 = ((s >> 1) & 1) ? -tsum : tsum;          // q=2 <-> bit1
    float v3 = (s & 1)        ? -tsum : tsum;          // q=3 <-> bit0
#pragma unroll
    for (int d = 1; d < 8; d <<= 1) {
        v0 += SHFL8(v0, d);
        v1 += SHFL8(v1, d);
        v2 += SHFL8(v2, d);
        v3 += SHFL8(v3, d);
    }
    if (s == 0 && sm < 81) {
        bufA[0 * 81 + sm] = v0;
        bufA[1 * 81 + sm] = v1;
        bufA[2 * 81 + sm] = v2;
        bufA[3 * 81 + sm] = v3;
    }
    __syncthreads();

    // Inverse Vandermonde per axis (samples {0,pi/2,pi}, basis (1,cos,sin)):
    //   c0 = (s0+s2)/2 ; c1 = (s0-s2)/2 ; c2 = s1 - (s0+s2)/2
    const float Vi[3][3] = {{0.5f, 0.0f, 0.5f},
                            {0.5f, 0.0f, -0.5f},
                            {-0.5f, 1.0f, -0.5f}};
    const int WST[4] = {27, 9, 3, 1};
    float* src = bufA;
    float* dst = bufB;
    for (int ax = 3; ax >= 0; ax--) {
        if (t < 324) {
            const int o = t / 81, e = t % 81;
            const int ws2 = WST[ax];
            const int k = (e / ws2) % 3;
            const int eb = e - k * ws2;
            const float* sp = src + o * 81;
            dst[t] = Vi[k][0] * sp[eb] + Vi[k][1] * sp[eb + ws2] + Vi[k][2] * sp[eb + 2 * ws2];
        }
        __syncthreads();
        float* tmp = src; src = dst; dst = tmp;
    }

    if (t < 432) {
        const int o = t / 108, r = t % 108, k012 = r / 4, c = r % 4;
        g_T[t] = (c < 3) ? src[o * 81 + k012 * 3 + c] : 0.0f;
    }
}

// ---------------------------------------------------------------------------
// Kernel 2 (unchanged champion): 2 elements/thread, PDL-gated T read.
// ---------------------------------------------------------------------------
__global__ __launch_bounds__(256, 4) void qlayer_kernel(
    const float* __restrict__ x, float* __restrict__ out, int B)
{
    __shared__ __align__(16) float4 shT[108];   // [o*27 + k0*9 + k1*3 + k2], .xyz = k3
    const int t = threadIdx.x;

    const long long e0 = ((long long)blockIdx.x * 256 + t) * 2;
    const bool active = (e0 < B);

    // Prolog (independent of T): overlaps with build_T under PDL.
    float C[2][4], S[2][4];
    if (active) {
        const float4* __restrict__ x4 = (const float4*)x;
#pragma unroll
        for (int el = 0; el < 2; el++) {
            long long ei = e0 + el; if (ei >= B) ei = B - 1;
            float4 v = x4[ei];
            __sincosf(v.x, &S[el][0], &C[el][0]);
            __sincosf(v.y, &S[el][1], &C[el][1]);
            __sincosf(v.z, &S[el][2], &C[el][2]);
            __sincosf(v.w, &S[el][3], &C[el][3]);
        }
    }

    cudaGridDependencySynchronize();

    if (t < 108) shT[t] = __ldcg(((const float4*)g_T) + t);
    __syncthreads();

    if (active) {
        float outv[2][4];  // [el][o]
#pragma unroll
        for (int o = 0; o < 4; o++) {
            float acc[2];
#pragma unroll
            for (int k0 = 0; k0 < 3; k0++) {
                float Aacc[2];
#pragma unroll
                for (int k1 = 0; k1 < 3; k1++) {
                    float Bacc[2];
#pragma unroll
                    for (int k2 = 0; k2 < 3; k2++) {
                        const float4 tq = shT[o * 27 + k0 * 9 + k1 * 3 + k2];
#pragma unroll
                        for (int el = 0; el < 2; el++) {
                            float D = fmaf(tq.z, S[el][3], fmaf(tq.y, C[el][3], tq.x));
                            if (k2 == 0)      Bacc[el] = D;
                            else if (k2 == 1) Bacc[el] = fmaf(C[el][2], D, Bacc[el]);
                            else              Bacc[el] = fmaf(S[el][2], D, Bacc[el]);
                        }
                    }
#pragma unroll
                    for (int el = 0; el < 2; el++) {
                        if (k1 == 0)      Aacc[el] = Bacc[el];
                        else if (k1 == 1) Aacc[el] = fmaf(C[el][1], Bacc[el], Aacc[el]);
                        else              Aacc[el] = fmaf(S[el][1], Bacc[el], Aacc[el]);
                    }
                }
#pragma unroll
                for (int el = 0; el < 2; el++) {
                    if (k0 == 0)      acc[el] = Aacc[el];
                    else if (k0 == 1) acc[el] = fmaf(C[el][0], Aacc[el], acc[el]);
                    else              acc[el] = fmaf(S[el][0], Aacc[el], acc[el]);
                }
            }
#pragma unroll
            for (int el = 0; el < 2; el++) outv[el][o] = acc[el];
        }

        float4* __restrict__ o4 = (float4*)out;
#pragma unroll
        for (int el = 0; el < 2; el++) {
            long long ei = e0 + el;
            if (ei < B) o4[ei] = make_float4(outv[el][0], outv[el][1], outv[el][2], outv[el][3]);
        }
    }
}

// ---------------------------------------------------------------------------
extern "C" void kernel_launch(void* const* d_in, const int* in_sizes, int n_in,
                              void* d_out, int out_size) {
    const float* xp = (const float*)d_in[0];
    const float* wp = (const float*)d_in[1];
    int sx = in_sizes[0];
    if (n_in >= 2 && in_sizes[0] == 12 && in_sizes[1] != 12) {
        xp = (const float*)d_in[1];
        wp = (const float*)d_in[0];
        sx = in_sizes[1];
    }
    const int B = sx / 4;

    build_T_kernel<<<1, 672>>>(wp);

    const int elems_per_block = 256 * 2;
    const int grid = (B + elems_per_block - 1) / elems_per_block;

    cudaLaunchConfig_t cfg = {};
    cfg.gridDim = dim3((unsigned)grid);
    cfg.blockDim = dim3(256);
    cfg.dynamicSmemBytes = 0;
    cfg.stream = 0;
    cudaLaunchAttribute attr[1];
    attr[0].id = cudaLaunchAttributeProgrammaticStreamSerialization;
    attr[0].val.programmaticStreamSerializationAllowed = 1;
    cfg.attrs = attr;
    cfg.numAttrs = 1;
    cudaError_t err = cudaLaunchKernelEx(&cfg, qlayer_kernel, xp, (float*)d_out, B);
    if (err != cudaSuccess) {
        qlayer_kernel<<<grid, 256>>>(xp, (float*)d_out, B);
    }
}